// round 2
// baseline (speedup 1.0000x reference)
#include <cuda_runtime.h>

#define NN 100000
#define NE 600000
#define NV 50000
#define DIM 128
#define NNZ (NE + NN)
#define CHUNK ((NN + 1023) / 1024)   // 98

// ---------------- scratch (static device globals; no allocation) ----------
__device__ int   g_deg[NN];
__device__ int   g_rowptr[NN + 1];
__device__ int   g_cursor[NN];
__device__ int   g_col[NNZ];
__device__ float g_dinv[NN];
__device__ float g_Wp1[DIM * DIM];           // W1 interleaved (even/odd k pairs)
__device__ float g_Wp2[DIM * DIM];           // W2 interleaved
__device__ float g_embW[(size_t)NV * DIM];   // emb @ W1   (25.6 MB)
__device__ float g_agg [(size_t)NN * DIM];   // layer-1 output (51.2 MB)
__device__ float g_hw  [(size_t)NN * DIM];   // layer-2 pre-agg (51.2 MB)

// ---------------- degree / CSR build ---------------------------------------
__global__ void k_init_deg() {
    int i = blockIdx.x * blockDim.x + threadIdx.x;
    if (i < NN) g_deg[i] = 1;                // self-loop
}

__global__ void k_count_deg(const int* __restrict__ dst) {
    int e = blockIdx.x * blockDim.x + threadIdx.x;
    if (e < NE) atomicAdd(&g_deg[dst[e]], 1);
}

// Single-block exclusive scan of g_deg -> g_rowptr. Each thread owns a
// contiguous CHUNK; serial sum, block-scan the 1024 partials, serial write.
__global__ __launch_bounds__(1024) void k_scan_fused() {
    __shared__ int s[1024];
    int tid = threadIdx.x;
    int lo = tid * CHUNK;
    int hi = lo + CHUNK; if (hi > NN) hi = NN;

    int sum = 0;
    #pragma unroll 4
    for (int i = lo; i < hi; i++) sum += g_deg[i];
    s[tid] = sum;
    __syncthreads();
    #pragma unroll
    for (int off = 1; off < 1024; off <<= 1) {
        int t = (tid >= off) ? s[tid - off] : 0;
        __syncthreads();
        s[tid] += t;
        __syncthreads();
    }
    int run = (tid == 0) ? 0 : s[tid - 1];     // exclusive prefix
    #pragma unroll 4
    for (int i = lo; i < hi; i++) {
        g_rowptr[i] = run;
        run += g_deg[i];
    }
    if (tid == 1023) g_rowptr[NN] = run;
}

__global__ void k_fill_init() {
    int i = blockIdx.x * blockDim.x + threadIdx.x;
    if (i < NN) {
        int base = g_rowptr[i];
        g_col[base] = i;                     // self-loop entry first
        g_cursor[i] = base + 1;
        g_dinv[i] = rsqrtf((float)g_deg[i]);
    }
}

__global__ void k_fill_edges(const int* __restrict__ src, const int* __restrict__ dst) {
    int e = blockIdx.x * blockDim.x + threadIdx.x;
    if (e < NE) {
        int pos = atomicAdd(&g_cursor[dst[e]], 1);
        g_col[pos] = src[e];
    }
}

// ---------------- W interleave: Wp[kp][c] = pair(W[2kp][c], W[2kp+1][c]) ---
__global__ void k_prep_w(const float* __restrict__ W1, const float* __restrict__ W2) {
    int idx = blockIdx.x * blockDim.x + threadIdx.x;   // 2 * 64 * 128
    const float* W = (idx < 64 * DIM) ? W1 : W2;
    float* Wp      = (idx < 64 * DIM) ? g_Wp1 : g_Wp2;
    int j = idx & (64 * DIM - 1);
    int kp = j >> 7, c = j & 127;
    Wp[j * 2 + 0] = W[(2 * kp)     * DIM + c];
    Wp[j * 2 + 1] = W[(2 * kp + 1) * DIM + c];
}

// ---------------- f32x2 packed FMA -----------------------------------------
__device__ __forceinline__ unsigned long long ffma2(
    unsigned long long a, unsigned long long b, unsigned long long c) {
    unsigned long long d;
    asm("fma.rn.f32x2 %0, %1, %2, %3;" : "=l"(d) : "l"(a), "l"(b), "l"(c));
    return d;
}

// ---------------- dense GEMM via FFMA2: C[M,128] = A[M,128] @ W[128,128] ----
// Even/odd k partial sums live in the two halves of each 64-bit accumulator.
// 64 rows/block, 256 threads, 8 rows x 4 cols per thread.
__global__ __launch_bounds__(256) void k_gemm128x2(
    const float* __restrict__ A, const float* __restrict__ Wp,
    float* __restrict__ C, int M)
{
    __shared__ float sA[64 * DIM];
    int tid = threadIdx.x;
    int row0 = blockIdx.x * 64;
    int rows_left = M - row0;

    const float4* Av = (const float4*)(A + (size_t)row0 * DIM);
    float4* sAv = (float4*)sA;
    #pragma unroll
    for (int i = 0; i < 8; i++) {
        int idx = tid + i * 256;
        int r = idx >> 5;
        float4 v = make_float4(0.f, 0.f, 0.f, 0.f);
        if (r < rows_left) v = Av[idx];
        sAv[idx] = v;
    }
    __syncthreads();

    int lane = tid & 31;
    int ty   = tid >> 5;
    int r0   = ty * 8;
    int c0   = lane * 4;

    unsigned long long acc[8][4];
    #pragma unroll
    for (int r = 0; r < 8; r++)
        acc[r][0] = acc[r][1] = acc[r][2] = acc[r][3] = 0ull;

    // Wp row kp: 128 pairs (= 256 floats). Thread reads pairs c0..c0+3 = 32B.
    const ulonglong2* wbase = (const ulonglong2*)Wp + (c0 >> 1);

    #pragma unroll 4
    for (int kp = 0; kp < 64; kp++) {
        ulonglong2 wA = __ldg(wbase + kp * 64);       // pairs (c0, c0+1)
        ulonglong2 wB = __ldg(wbase + kp * 64 + 1);   // pairs (c0+2, c0+3)
        #pragma unroll
        for (int r = 0; r < 8; r++) {
            unsigned long long a =
                *(const unsigned long long*)&sA[(r0 + r) * DIM + kp * 2]; // broadcast LDS.64
            acc[r][0] = ffma2(a, wA.x, acc[r][0]);
            acc[r][1] = ffma2(a, wA.y, acc[r][1]);
            acc[r][2] = ffma2(a, wB.x, acc[r][2]);
            acc[r][3] = ffma2(a, wB.y, acc[r][3]);
        }
    }

    #pragma unroll
    for (int r = 0; r < 8; r++) {
        int rr = row0 + r0 + r;
        if (rr < M) {
            float4 o;
            float2 p0 = *(float2*)&acc[r][0];
            float2 p1 = *(float2*)&acc[r][1];
            float2 p2 = *(float2*)&acc[r][2];
            float2 p3 = *(float2*)&acc[r][3];
            o.x = p0.x + p0.y;
            o.y = p1.x + p1.y;
            o.z = p2.x + p2.y;
            o.w = p3.x + p3.y;
            *(float4*)(C + (size_t)rr * DIM + c0) = o;
        }
    }
}

// ---------------- SpMM gather: out[i] = relu(dinv[i]*Σ dinv[j]*feat[row(j)] + b)
template<bool LAYER1>
__global__ __launch_bounds__(256) void k_spmm(
    const float* __restrict__ feat, const int* __restrict__ x,
    const float* __restrict__ bias, float* __restrict__ out)
{
    int node = (int)((blockIdx.x * blockDim.x + threadIdx.x) >> 5);
    if (node >= NN) return;
    int lane = threadIdx.x & 31;

    int start = g_rowptr[node];
    int end   = g_rowptr[node + 1];
    const float4* f4 = (const float4*)feat;

    float ax = 0.f, ay = 0.f, az = 0.f, aw = 0.f;
    int k = start;
    for (; k + 1 < end; k += 2) {
        int c0 = g_col[k];
        int c1 = g_col[k + 1];
        float w0 = g_dinv[c0];
        float w1 = g_dinv[c1];
        int r0 = LAYER1 ? x[c0] : c0;
        int r1 = LAYER1 ? x[c1] : c1;
        float4 v0 = f4[(size_t)r0 * 32 + lane];
        float4 v1 = f4[(size_t)r1 * 32 + lane];
        ax = fmaf(w0, v0.x, ax); ay = fmaf(w0, v0.y, ay);
        az = fmaf(w0, v0.z, az); aw = fmaf(w0, v0.w, aw);
        ax = fmaf(w1, v1.x, ax); ay = fmaf(w1, v1.y, ay);
        az = fmaf(w1, v1.z, az); aw = fmaf(w1, v1.w, aw);
    }
    if (k < end) {
        int c = g_col[k];
        float w = g_dinv[c];
        int r = LAYER1 ? x[c] : c;
        float4 v = f4[(size_t)r * 32 + lane];
        ax = fmaf(w, v.x, ax); ay = fmaf(w, v.y, ay);
        az = fmaf(w, v.z, az); aw = fmaf(w, v.w, aw);
    }

    float di = g_dinv[node];
    float4 b = __ldg((const float4*)bias + lane);
    float4 o;
    o.x = fmaxf(fmaf(di, ax, b.x), 0.f);
    o.y = fmaxf(fmaf(di, ay, b.y), 0.f);
    o.z = fmaxf(fmaf(di, az, b.z), 0.f);
    o.w = fmaxf(fmaf(di, aw, b.w), 0.f);
    ((float4*)out)[(size_t)node * 32 + lane] = o;
}

// ---------------- launch ----------------------------------------------------
extern "C" void kernel_launch(void* const* d_in, const int* in_sizes, int n_in,
                              void* d_out, int out_size) {
    const int*   x   = (const int*)d_in[0];
    const int*   src = (const int*)d_in[1];          // edge_index[0]
    const int*   dst = src + NE;                     // edge_index[1]
    const float* emb = (const float*)d_in[2];
    const float* W1  = (const float*)d_in[3];
    const float* b1  = (const float*)d_in[4];
    const float* W2  = (const float*)d_in[5];
    const float* b2  = (const float*)d_in[6];
    float*       out = (float*)d_out;

    float *p_embW, *p_agg, *p_hw, *p_Wp1, *p_Wp2;
    cudaGetSymbolAddress((void**)&p_embW, g_embW);
    cudaGetSymbolAddress((void**)&p_agg,  g_agg);
    cudaGetSymbolAddress((void**)&p_hw,   g_hw);
    cudaGetSymbolAddress((void**)&p_Wp1,  g_Wp1);
    cudaGetSymbolAddress((void**)&p_Wp2,  g_Wp2);

    // CSR build (by dst, self-loops included)
    k_init_deg  <<<(NN + 255) / 256, 256>>>();
    k_count_deg <<<(NE + 255) / 256, 256>>>(dst);
    k_scan_fused<<<1, 1024>>>();
    k_fill_init <<<(NN + 255) / 256, 256>>>();
    k_fill_edges<<<(NE + 255) / 256, 256>>>(src, dst);

    // W interleave for f32x2 GEMM
    k_prep_w<<<(2 * 64 * DIM + 255) / 256, 256>>>(W1, W2);

    // Layer 1: embW = emb @ W1 (vocab-sized GEMM), then gathered aggregation
    k_gemm128x2<<<(NV + 63) / 64, 256>>>(emb, p_Wp1, p_embW, NV);
    k_spmm<true><<<(NN + 7) / 8, 256>>>(p_embW, x, b1, p_agg);

    // Layer 2: hw = agg @ W2, then aggregation into d_out
    k_gemm128x2<<<(NN + 63) / 64, 256>>>(p_agg, p_Wp2, p_hw, NN);
    k_spmm<false><<<(NN + 7) / 8, 256>>>(p_hw, x, b2, out);
}

// round 4
// speedup vs baseline: 1.2040x; 1.2040x over previous
#include <cuda_runtime.h>
#include <cuda_bf16.h>
#include <cstdint>

#define NN 100000
#define NE 600000
#define NV 50000
#define DIM 128
#define NNZ (NE + NN)
#define CHUNK ((NN + 1023) / 1024)   // 98

#define TILES1 ((NV + 127) / 128)    // 391
#define TILES2 ((NN + 127) / 128)    // 782

// ---------------- scratch (static device globals; no allocation) ----------
__device__ int   g_deg[NN];
__device__ int   g_rowptr[NN + 1];
__device__ int   g_cursor[NN];
__device__ int   g_col[NNZ];
__device__ float g_dinv[NN];
// W fragments in mma.sync B-fragment order: [layer][nt(16)][kt(8)][lane(32)] uint2
__device__ uint2 g_Wfh[2 * 16 * 8 * 32];     // hi parts (32KB/layer)
__device__ uint2 g_Wfl[2 * 16 * 8 * 32];     // lo parts
__device__ float g_embW[(size_t)NV * DIM];   // emb @ W1
__device__ float g_agg [(size_t)NN * DIM];   // layer-1 output
__device__ float g_hw  [(size_t)NN * DIM];   // layer-2 pre-agg

// ---------------- degree / CSR build ---------------------------------------
__global__ void k_init_deg() {
    int i = blockIdx.x * blockDim.x + threadIdx.x;
    if (i < NN) g_deg[i] = 1;                // self-loop
}
__global__ void k_count_deg(const int* __restrict__ dst) {
    int e = blockIdx.x * blockDim.x + threadIdx.x;
    if (e < NE) atomicAdd(&g_deg[dst[e]], 1);
}
__global__ __launch_bounds__(1024) void k_scan_fused() {
    __shared__ int s[1024];
    int tid = threadIdx.x;
    int lo = tid * CHUNK;
    int hi = lo + CHUNK; if (hi > NN) hi = NN;
    int sum = 0;
    #pragma unroll 4
    for (int i = lo; i < hi; i++) sum += g_deg[i];
    s[tid] = sum;
    __syncthreads();
    #pragma unroll
    for (int off = 1; off < 1024; off <<= 1) {
        int t = (tid >= off) ? s[tid - off] : 0;
        __syncthreads();
        s[tid] += t;
        __syncthreads();
    }
    int run = (tid == 0) ? 0 : s[tid - 1];
    #pragma unroll 4
    for (int i = lo; i < hi; i++) { g_rowptr[i] = run; run += g_deg[i]; }
    if (tid == 1023) g_rowptr[NN] = run;
}
__global__ void k_fill_init() {
    int i = blockIdx.x * blockDim.x + threadIdx.x;
    if (i < NN) {
        int base = g_rowptr[i];
        g_col[base] = i;                     // self-loop entry first
        g_cursor[i] = base + 1;
        g_dinv[i] = rsqrtf((float)g_deg[i]);
    }
}
__global__ void k_fill_edges(const int* __restrict__ src, const int* __restrict__ dst) {
    int e = blockIdx.x * blockDim.x + threadIdx.x;
    if (e < NE) {
        int pos = atomicAdd(&g_cursor[dst[e]], 1);
        g_col[pos] = src[e];
    }
}

// ---------------- helpers ---------------------------------------------------
__device__ __forceinline__ uint32_t pack_bf16(float lo_val, float hi_val) {
    uint32_t d;
    asm("cvt.rn.bf16x2.f32 %0, %1, %2;" : "=r"(d) : "f"(hi_val), "f"(lo_val));
    return d;
}
__device__ __forceinline__ void mma_bf16(float* c, const uint32_t* a, uint2 b) {
    asm volatile(
        "mma.sync.aligned.m16n8k16.row.col.f32.bf16.bf16.f32 "
        "{%0,%1,%2,%3}, {%4,%5,%6,%7}, {%8,%9}, {%0,%1,%2,%3};"
        : "+f"(c[0]), "+f"(c[1]), "+f"(c[2]), "+f"(c[3])
        : "r"(a[0]), "r"(a[1]), "r"(a[2]), "r"(a[3]), "r"(b.x), "r"(b.y));
}

// ---- W fragment prep: B frag (m16n8k16 col) for C = A @ W, split hi/lo ----
// thread -> (layer, nt, kt, lane). B[k][n] = W[k][n].
// frag: b0 = {W[k0][n], W[k0+1][n]}, b1 = {W[k0+8][n], W[k0+9][n]},
//       k0 = kt*16 + (lane%4)*2, n = nt*8 + lane/4.
__global__ void k_prep_wf(const float* __restrict__ W1, const float* __restrict__ W2) {
    int gid = blockIdx.x * blockDim.x + threadIdx.x;   // 8192 total
    if (gid >= 2 * 16 * 8 * 32) return;
    int lane  = gid & 31;
    int kt    = (gid >> 5) & 7;
    int nt    = (gid >> 8) & 15;
    int layer = gid >> 12;
    const float* W = layer ? W2 : W1;
    int n  = nt * 8 + (lane >> 2);
    int k0 = kt * 16 + (lane & 3) * 2;

    float v[4];
    v[0] = W[(k0    ) * DIM + n];
    v[1] = W[(k0 + 1) * DIM + n];
    v[2] = W[(k0 + 8) * DIM + n];
    v[3] = W[(k0 + 9) * DIM + n];
    float h[4], l[4];
    #pragma unroll
    for (int j = 0; j < 4; j++) {
        __nv_bfloat16 hb = __float2bfloat16_rn(v[j]);
        h[j] = __bfloat162float(hb);
        l[j] = v[j] - h[j];
    }
    int idx = gid;   // same layout: ((layer*16+nt)*8+kt)*32+lane
    g_Wfh[idx] = make_uint2(pack_bf16(h[0], h[1]), pack_bf16(h[2], h[3]));
    g_Wfl[idx] = make_uint2(pack_bf16(l[0], l[1]), pack_bf16(l[2], l[3]));
}

// ---------------- GEMM via mma.sync bf16 split (3-pass) --------------------
// C[M,128] = A[M,128] @ W. 128 rows/block, 8 warps x 16 rows, acc 16x[4] f32.
#define A_PAD 132     // floats per smem row

__global__ __launch_bounds__(256, 2) void k_gemm_mma(
    const float* __restrict__ A,
    const uint2* __restrict__ WfH, const uint2* __restrict__ WfL,
    float* __restrict__ C, int M)
{
    extern __shared__ float sA[];            // 128 * A_PAD floats
    int tid = threadIdx.x;
    int wid = tid >> 5;
    int lane = tid & 31;
    int row0 = blockIdx.x * 128;
    int rows_left = M - row0;

    // stage A tile (coalesced float4, zero-pad tail rows)
    {
        const float4* Av = (const float4*)(A + (size_t)row0 * DIM);
        float4* sA4 = (float4*)sA;
        #pragma unroll
        for (int i = 0; i < 16; i++) {
            int idx = tid + i * 256;
            int r = idx >> 5, c4 = idx & 31;
            float4 v = make_float4(0.f, 0.f, 0.f, 0.f);
            if (r < rows_left) v = Av[idx];
            sA4[r * (A_PAD / 4) + c4] = v;
        }
    }
    __syncthreads();

    float acc[16][4];
    #pragma unroll
    for (int nt = 0; nt < 16; nt++)
        acc[nt][0] = acc[nt][1] = acc[nt][2] = acc[nt][3] = 0.f;

    int r  = wid * 16 + (lane >> 2);
    int k2base = (lane & 3) * 2;

    #pragma unroll
    for (int kt = 0; kt < 8; kt++) {
        int k2 = kt * 16 + k2base;
        float2 f0 = *(const float2*)&sA[ r      * A_PAD + k2    ];
        float2 f1 = *(const float2*)&sA[(r + 8) * A_PAD + k2    ];
        float2 f2 = *(const float2*)&sA[ r      * A_PAD + k2 + 8];
        float2 f3 = *(const float2*)&sA[(r + 8) * A_PAD + k2 + 8];

        uint32_t ah[4], al[4];
        {
            float fx[4] = {f0.x, f1.x, f2.x, f3.x};
            float fy[4] = {f0.y, f1.y, f2.y, f3.y};
            #pragma unroll
            for (int j = 0; j < 4; j++) {
                __nv_bfloat16 hx = __float2bfloat16_rn(fx[j]);
                __nv_bfloat16 hy = __float2bfloat16_rn(fy[j]);
                float hxf = __bfloat162float(hx);
                float hyf = __bfloat162float(hy);
                ah[j] = pack_bf16(hxf, hyf);
                al[j] = pack_bf16(fx[j] - hxf, fy[j] - hyf);
            }
        }

        const uint2* ph = WfH + kt * 32 + lane;
        const uint2* pl = WfL + kt * 32 + lane;
        #pragma unroll
        for (int nt = 0; nt < 16; nt++) {
            uint2 bh = __ldg(ph + nt * 256);     // (nt*8+kt)*32+lane
            uint2 bl = __ldg(pl + nt * 256);
            mma_bf16(acc[nt], ah, bh);
            mma_bf16(acc[nt], al, bh);
            mma_bf16(acc[nt], ah, bl);
        }
    }

    // epilogue: c0,c1 -> row r cols 2(lane%4)+{0,1}; c2,c3 -> row r+8
    int rr0 = row0 + r;
    int rr1 = rr0 + 8;
    #pragma unroll
    for (int nt = 0; nt < 16; nt++) {
        int col = nt * 8 + k2base;
        if (rr0 < M)
            *(float2*)&C[(size_t)rr0 * DIM + col] = make_float2(acc[nt][0], acc[nt][1]);
        if (rr1 < M)
            *(float2*)&C[(size_t)rr1 * DIM + col] = make_float2(acc[nt][2], acc[nt][3]);
    }
}

// ---------------- SpMM gather: out[i] = relu(dinv[i]*Σ dinv[j]*feat[row(j)] + b)
template<bool LAYER1>
__global__ __launch_bounds__(256) void k_spmm(
    const float* __restrict__ feat, const int* __restrict__ x,
    const float* __restrict__ bias, float* __restrict__ out)
{
    int node = (int)((blockIdx.x * blockDim.x + threadIdx.x) >> 5);
    if (node >= NN) return;
    int lane = threadIdx.x & 31;

    int start = g_rowptr[node];
    int end   = g_rowptr[node + 1];
    const float4* f4 = (const float4*)feat;

    float ax = 0.f, ay = 0.f, az = 0.f, aw = 0.f;
    int k = start;
    for (; k + 1 < end; k += 2) {
        int c0 = g_col[k];
        int c1 = g_col[k + 1];
        float w0 = g_dinv[c0];
        float w1 = g_dinv[c1];
        int r0 = LAYER1 ? x[c0] : c0;
        int r1 = LAYER1 ? x[c1] : c1;
        float4 v0 = f4[(size_t)r0 * 32 + lane];
        float4 v1 = f4[(size_t)r1 * 32 + lane];
        ax = fmaf(w0, v0.x, ax); ay = fmaf(w0, v0.y, ay);
        az = fmaf(w0, v0.z, az); aw = fmaf(w0, v0.w, aw);
        ax = fmaf(w1, v1.x, ax); ay = fmaf(w1, v1.y, ay);
        az = fmaf(w1, v1.z, az); aw = fmaf(w1, v1.w, aw);
    }
    if (k < end) {
        int c = g_col[k];
        float w = g_dinv[c];
        int r = LAYER1 ? x[c] : c;
        float4 v = f4[(size_t)r * 32 + lane];
        ax = fmaf(w, v.x, ax); ay = fmaf(w, v.y, ay);
        az = fmaf(w, v.z, az); aw = fmaf(w, v.w, aw);
    }

    float di = g_dinv[node];
    float4 b = __ldg((const float4*)bias + lane);
    float4 o;
    o.x = fmaxf(fmaf(di, ax, b.x), 0.f);
    o.y = fmaxf(fmaf(di, ay, b.y), 0.f);
    o.z = fmaxf(fmaf(di, az, b.z), 0.f);
    o.w = fmaxf(fmaf(di, aw, b.w), 0.f);
    ((float4*)out)[(size_t)node * 32 + lane] = o;
}

// ---------------- launch ----------------------------------------------------
extern "C" void kernel_launch(void* const* d_in, const int* in_sizes, int n_in,
                              void* d_out, int out_size) {
    const int*   x   = (const int*)d_in[0];
    const int*   src = (const int*)d_in[1];          // edge_index[0]
    const int*   dst = src + NE;                     // edge_index[1]
    const float* emb = (const float*)d_in[2];
    const float* W1  = (const float*)d_in[3];
    const float* b1  = (const float*)d_in[4];
    const float* W2  = (const float*)d_in[5];
    const float* b2  = (const float*)d_in[6];
    float*       out = (float*)d_out;

    float *p_embW, *p_agg, *p_hw;
    uint2 *p_Wfh, *p_Wfl;
    cudaGetSymbolAddress((void**)&p_embW, g_embW);
    cudaGetSymbolAddress((void**)&p_agg,  g_agg);
    cudaGetSymbolAddress((void**)&p_hw,   g_hw);
    cudaGetSymbolAddress((void**)&p_Wfh,  g_Wfh);
    cudaGetSymbolAddress((void**)&p_Wfl,  g_Wfl);

    const int SMEM_GEMM = 128 * A_PAD * 4;           // 67584 B
    cudaFuncSetAttribute(k_gemm_mma, cudaFuncAttributeMaxDynamicSharedMemorySize, SMEM_GEMM);

    // CSR build (by dst, self-loops included)
    k_init_deg  <<<(NN + 255) / 256, 256>>>();
    k_count_deg <<<(NE + 255) / 256, 256>>>(dst);
    k_scan_fused<<<1, 1024>>>();
    k_fill_init <<<(NN + 255) / 256, 256>>>();
    k_fill_edges<<<(NE + 255) / 256, 256>>>(src, dst);

    // W -> mma fragments (hi/lo split)
    k_prep_wf<<<(2 * 16 * 8 * 32 + 255) / 256, 256>>>(W1, W2);

    // Layer 1: embW = emb @ W1 (vocab-sized GEMM), then gathered aggregation
    k_gemm_mma<<<TILES1, 256, SMEM_GEMM>>>(emb, p_Wfh, p_Wfl, p_embW, NV);
    k_spmm<true><<<(NN + 7) / 8, 256>>>(p_embW, x, b1, p_agg);

    // Layer 2: hw = agg @ W2, then aggregation into d_out
    k_gemm_mma<<<TILES2, 256, SMEM_GEMM>>>(p_agg, p_Wfh + 16 * 8 * 32, p_Wfl + 16 * 8 * 32, p_hw, NN);
    k_spmm<false><<<(NN + 7) / 8, 256>>>(p_hw, x, b2, out);
}